// round 4
// baseline (speedup 1.0000x reference)
#include <cuda_runtime.h>
#include <cstdint>

// ---------------- problem constants ----------------
#define IN_SZ    64
#define HID      128
#define OUT_SZ   64
#define NHEAD    16
#define MT       128         // batch rows per CTA
#define NTHREADS 256         // 8 warps, 16 rows each

// ---------------- smem layout (bytes) ----------------
// W1F: 16 ntiles x 8 ksteps x 32 lanes x 2 u32  = 8192 u32 = 32 KB
// W2F:  8 ntiles x 16 ksteps x 32 lanes x 2 u32 = 8192 u32 = 32 KB
// ACT:  8 warps x 1024 u32 (A-fragment layout, 8 ksteps x 128) = 32 KB
//       (first used for x fragments, then reused per-warp for elu(h) fragments)
#define W1F_OFF 0
#define W2F_OFF 32768
#define ACT_OFF 65536
#define B1S_OFF 98304        // 128 floats
#define B2S_OFF 98816        // 64 floats
#define SMEM_TOTAL 99072

// ---------------- helpers ----------------
__device__ __forceinline__ uint32_t f2tf32(float f) {
    uint32_t r;
    asm("cvt.rna.tf32.f32 %0, %1;" : "=r"(r) : "f"(f));
    return r;
}

// D += A * B  (tf32, m16n8k8, row.col, fp32 accum)
__device__ __forceinline__ void mma8(float c[4], const uint4 a, const uint2 b) {
    asm volatile(
        "mma.sync.aligned.m16n8k8.row.col.f32.tf32.tf32.f32 "
        "{%0,%1,%2,%3}, {%4,%5,%6,%7}, {%8,%9}, {%0,%1,%2,%3};\n"
        : "+f"(c[0]), "+f"(c[1]), "+f"(c[2]), "+f"(c[3])
        : "r"(a.x), "r"(a.y), "r"(a.z), "r"(a.w), "r"(b.x), "r"(b.y));
}

__device__ __forceinline__ float eluf(float v) {
    return v > 0.0f ? v : (__expf(v) - 1.0f);
}

// ---------------- kernel ----------------
__global__ void __launch_bounds__(NTHREADS, 2)
mlp16_kernel(const float* __restrict__ x,
             const float* __restrict__ W1,
             const float* __restrict__ b1,
             const float* __restrict__ W2,
             const float* __restrict__ b2,
             float* __restrict__ out)
{
    extern __shared__ char smem[];
    uint32_t* w1f = reinterpret_cast<uint32_t*>(smem + W1F_OFF);
    uint32_t* w2f = reinterpret_cast<uint32_t*>(smem + W2F_OFF);
    uint32_t* act = reinterpret_cast<uint32_t*>(smem + ACT_OFF);
    float* b1s = reinterpret_cast<float*>(smem + B1S_OFF);
    float* b2s = reinterpret_cast<float*>(smem + B2S_OFF);

    const int tid = threadIdx.x;
    const int wid = tid >> 5;
    const int lid = tid & 31;
    const int g   = lid >> 2;       // row group 0..7
    const int tc  = lid & 3;        // thread-in-group 0..3
    const int h   = blockIdx.x;
    const int m0  = blockIdx.y * MT;

    // ---- biases ----
    if (tid < HID)    b1s[tid] = b1[h * HID + tid];
    if (tid < OUT_SZ) b2s[tid] = b2[h * OUT_SZ + tid];

    // ---- stage W1[h] (64 x 128, k-major rows) into B-fragment layout ----
    // b0: k = 8*s + c,  b1: k = 8*s + c + 4,  n = 8*t + g
    {
        const float* W1h = W1 + (size_t)h * IN_SZ * HID;
        for (int e = tid; e < IN_SZ * HID; e += NTHREADS) {
            int i = e >> 7;          // k (input) 0..63
            int n = e & 127;         // hid 0..127  (coalesced in e)
            float wv = W1h[e];
            int t = n >> 3, gg = n & 7;
            int s = i >> 3, kk = i & 7, c = kk & 3, bb = kk >> 2;
            w1f[(((t * 8 + s) * 32) + gg * 4 + c) * 2 + bb] = f2tf32(wv);
        }
    }

    // ---- stage W2[h] (128 x 64) into B-fragment layout ----
    {
        const float* W2h = W2 + (size_t)h * HID * OUT_SZ;
        for (int e = tid; e < HID * OUT_SZ; e += NTHREADS) {
            int j = e >> 6;          // k (hid) 0..127
            int n = e & 63;          // out 0..63
            float wv = W2h[e];
            int t = n >> 3, gg = n & 7;
            int s = j >> 3, kk = j & 7, c = kk & 3, bb = kk >> 2;
            w2f[(((t * 16 + s) * 32) + gg * 4 + c) * 2 + bb] = f2tf32(wv);
        }
    }

    // ---- stage x tile (128 x 64) into per-warp A-fragment layout ----
    // A regs j: 0:(g, c) 1:(g+8, c) 2:(g, c+4) 3:(g+8, c+4);  k = 8*s + c(+4)
    {
        const float4* xt = reinterpret_cast<const float4*>(x + (size_t)m0 * IN_SZ);
        for (int t = tid; t < MT * IN_SZ / 4; t += NTHREADS) {   // 2048 float4
            float4 v = xt[t];
            int row = t >> 4;                 // 0..127
            int cb  = (t & 15) << 2;          // col base
            int w   = row >> 4;               // owning warp
            int rr  = row & 15;
            int gg  = rr & 7, bh = rr >> 3;   // g, row-half
            float vv[4] = {v.x, v.y, v.z, v.w};
            #pragma unroll
            for (int q = 0; q < 4; q++) {
                int col = cb + q;
                int s = col >> 3, cc = col & 7, c = cc & 3, a = cc >> 2;
                act[w * 1024 + s * 128 + (gg * 4 + c) * 4 + 2 * a + bh] = f2tf32(vv[q]);
            }
        }
    }
    __syncthreads();

    const uint32_t* actw = act + wid * 1024;
    uint32_t* actw_w = act + wid * 1024;

    // ---- GEMM1: C1[16 rows x 128] per warp = x[16,64] * W1[64,128] ----
    float C1[16][4];
    #pragma unroll
    for (int t = 0; t < 16; t++)
        #pragma unroll
        for (int r = 0; r < 4; r++) C1[t][r] = 0.0f;

    #pragma unroll
    for (int s = 0; s < 8; s++) {
        uint4 av = *reinterpret_cast<const uint4*>(actw + s * 128 + lid * 4);
        #pragma unroll
        for (int t = 0; t < 16; t++) {
            uint2 bv = *reinterpret_cast<const uint2*>(w1f + ((t * 8 + s) * 32 + lid) * 2);
            mma8(C1[t], av, bv);
        }
    }

    // ---- epilogue1 (bias + ELU -> tf32 A-frags) + GEMM2, in 2 K-chunks ----
    float C2[8][4];
    #pragma unroll
    for (int t = 0; t < 8; t++)
        #pragma unroll
        for (int r = 0; r < 4; r++) C2[t][r] = 0.0f;

    #pragma unroll
    for (int ch = 0; ch < 2; ch++) {
        __syncwarp();   // prior reads of actw (GEMM1 / previous chunk) done
        #pragma unroll
        for (int t1 = 0; t1 < 8; t1++) {
            int tt = ch * 8 + t1;
            #pragma unroll
            for (int r = 0; r < 4; r++) {
                int col = 8 * tt + 2 * tc + (r & 1);       // hid col 0..127
                float v = eluf(C1[tt][r] + b1s[col]);
                // layer-2 A fragment position: s2 == tt, within chunk slot t1
                int cc = col & 7, c2 = cc & 3, a2 = cc >> 2;
                actw_w[t1 * 128 + (g * 4 + c2) * 4 + 2 * a2 + (r >> 1)] = f2tf32(v);
            }
        }
        __syncwarp();
        #pragma unroll
        for (int s = 0; s < 8; s++) {
            uint4 av = *reinterpret_cast<const uint4*>(actw + s * 128 + lid * 4);
            int s2 = ch * 8 + s;
            #pragma unroll
            for (int t2 = 0; t2 < 8; t2++) {
                uint2 bv = *reinterpret_cast<const uint2*>(w2f + ((t2 * 16 + s2) * 32 + lid) * 2);
                mma8(C2[t2], av, bv);
            }
        }
    }

    // ---- epilogue2: + b2 -> out[b, h, :] ----
    {
        const int rbase = m0 + wid * 16 + g;
        #pragma unroll
        for (int half = 0; half < 2; half++) {
            const size_t rowoff = (size_t)(rbase + 8 * half) * (NHEAD * OUT_SZ) + h * OUT_SZ;
            #pragma unroll
            for (int t2 = 0; t2 < 8; t2++) {
                int col = 8 * t2 + 2 * tc;
                float2 o;
                o.x = C2[t2][half * 2 + 0] + b2s[col];
                o.y = C2[t2][half * 2 + 1] + b2s[col + 1];
                *reinterpret_cast<float2*>(out + rowoff + col) = o;
            }
        }
    }
}

// ---------------- launch ----------------
extern "C" void kernel_launch(void* const* d_in, const int* in_sizes, int n_in,
                              void* d_out, int out_size)
{
    const float* x  = (const float*)d_in[0];
    const float* W1 = (const float*)d_in[1];
    const float* b1 = (const float*)d_in[2];
    const float* W2 = (const float*)d_in[3];
    const float* b2 = (const float*)d_in[4];
    float* out = (float*)d_out;

    int B = in_sizes[0] / IN_SZ;        // 131072
    int mtiles = B / MT;                // 1024

    cudaFuncSetAttribute(mlp16_kernel,
                         cudaFuncAttributeMaxDynamicSharedMemorySize, SMEM_TOTAL);
    mlp16_kernel<<<dim3(NHEAD, mtiles), NTHREADS, SMEM_TOTAL>>>(x, W1, b1, W2, b2, out);
}

// round 5
// speedup vs baseline: 1.5907x; 1.5907x over previous
#include <cuda_runtime.h>
#include <cstdint>

// ---------------- problem constants ----------------
#define IN_SZ    64
#define HID      128
#define OUT_SZ   64
#define NHEAD    16
#define MT       128          // batch rows per rep
#define REPS     4            // reps per CTA (512 rows/CTA)
#define NTHREADS 256          // 8 warps: mg = wid&3 (row group), nh = wid>>2 (col half)

// ---------------- smem layout (u32 offsets) ----------------
#define W1F_U   0             // 8192 u32  (16 ntiles x 8 ks x 32 lanes x 2)
#define W2F_U   8192          // 8192 u32  (8 ntiles x 16 ks x 32 lanes x 2)
#define XH_U    16384         // 9216 u32: x tile (pitch 68) OR 2 h quarter-buffers (pitch 36)
#define B1S_U   25600         // 128 floats
#define B2S_U   25728         // 64 floats
#define SMEM_U  25792
#define SMEM_BYTES (SMEM_U * 4)   // 103168 B  -> 2 CTAs/SM

#define XPITCH  68            // 68 % 32 == 4 -> conflict-free frag gathers
#define HPITCH  36            // 36 % 32 == 4
#define HREG_U  4608          // one h quarter buffer: 128 rows * 36

// ---------------- helpers ----------------
__device__ __forceinline__ uint32_t f2tf32(float f) {
    uint32_t r;
    asm("cvt.rna.tf32.f32 %0, %1;" : "=r"(r) : "f"(f));
    return r;
}

__device__ __forceinline__ void mma8(float c[4], const uint4 a, const uint2 b) {
    asm volatile(
        "mma.sync.aligned.m16n8k8.row.col.f32.tf32.tf32.f32 "
        "{%0,%1,%2,%3}, {%4,%5,%6,%7}, {%8,%9}, {%0,%1,%2,%3};\n"
        : "+f"(c[0]), "+f"(c[1]), "+f"(c[2]), "+f"(c[3])
        : "r"(a.x), "r"(a.y), "r"(a.z), "r"(a.w), "r"(b.x), "r"(b.y));
}

__device__ __forceinline__ float eluf(float v) {
    return v > 0.0f ? v : (__expf(v) - 1.0f);
}

// ---------------- kernel ----------------
__global__ void __launch_bounds__(NTHREADS, 2)
mlp16_kernel(const float* __restrict__ x,
             const float* __restrict__ W1,
             const float* __restrict__ b1,
             const float* __restrict__ W2,
             const float* __restrict__ b2,
             float* __restrict__ out)
{
    extern __shared__ uint32_t sm[];
    float* b1s = reinterpret_cast<float*>(sm + B1S_U);
    float* b2s = reinterpret_cast<float*>(sm + B2S_U);

    const int tid = threadIdx.x;
    const int wid = tid >> 5;
    const int lid = tid & 31;
    const int g   = lid >> 2;         // 0..7
    const int tc  = lid & 3;          // 0..3
    const int mg  = wid & 3;          // 0..3 : rows [32mg, 32mg+32)
    const int nh  = wid >> 2;         // 0..1 : col half
    const int head = blockIdx.x;
    const size_t mbase = (size_t)blockIdx.y * (MT * REPS);

    // ---- biases ----
    if (tid < HID)    b1s[tid] = b1[head * HID + tid];
    if (tid < OUT_SZ) b2s[tid] = b2[head * OUT_SZ + tid];

    // ---- stage W1[h] (64 x 128) into B-fragment layout (coalesced LDG) ----
    {
        const float* W1h = W1 + (size_t)head * IN_SZ * HID;
        for (int e = tid; e < IN_SZ * HID; e += NTHREADS) {
            int i = e >> 7;           // k 0..63
            int n = e & 127;          // hid 0..127
            float wv = W1h[e];
            int t = n >> 3, gg = n & 7;
            int s = i >> 3, kk = i & 7, c = kk & 3, bb = kk >> 2;
            sm[W1F_U + (((t * 8 + s) * 32) + gg * 4 + c) * 2 + bb] = f2tf32(wv);
        }
    }

    // ---- stage W2[h] (128 x 64) into B-fragment layout ----
    {
        const float* W2h = W2 + (size_t)head * HID * OUT_SZ;
        for (int e = tid; e < HID * OUT_SZ; e += NTHREADS) {
            int j = e >> 6;           // k 0..127
            int n = e & 63;           // out 0..63
            float wv = W2h[e];
            int t = n >> 3, gg = n & 7;
            int s = j >> 3, kk = j & 7, c = kk & 3, bb = kk >> 2;
            sm[W2F_U + (((t * 16 + s) * 32) + gg * 4 + c) * 2 + bb] = f2tf32(wv);
        }
    }

    #pragma unroll 1
    for (int rep = 0; rep < REPS; rep++) {
        __syncthreads();   // (a) XH window free (prior-rep GEMM2 / W-stage done)

        // ---- stage x tile [128 x 64] -> row-major tf32, pitch 68 ----
        {
            const float4* xt = reinterpret_cast<const float4*>(
                x + (mbase + (size_t)rep * MT) * IN_SZ);
            #pragma unroll
            for (int i4 = 0; i4 < 8; i4++) {
                int t = i4 * NTHREADS + tid;       // 0..2047
                float4 v = xt[t];
                int row = t >> 4;
                int c4  = (t & 15) << 2;
                uint4 u;
                u.x = f2tf32(v.x); u.y = f2tf32(v.y);
                u.z = f2tf32(v.z); u.w = f2tf32(v.w);
                *reinterpret_cast<uint4*>(sm + XH_U + row * XPITCH + c4) = u;
            }
        }
        __syncthreads();   // (b)

        // ---- GEMM1: warp computes rows [32mg,+32) x hid cols [64nh,+64) ----
        float C1[2][8][4];
        #pragma unroll
        for (int mt = 0; mt < 2; mt++)
            #pragma unroll
            for (int t1 = 0; t1 < 8; t1++)
                #pragma unroll
                for (int r = 0; r < 4; r++) C1[mt][t1][r] = 0.0f;

        #pragma unroll
        for (int s = 0; s < 8; s++) {
            uint4 A[2];
            #pragma unroll
            for (int mt = 0; mt < 2; mt++) {
                int r0 = mg * 32 + mt * 16 + g;
                const uint32_t* xb = sm + XH_U;
                A[mt].x = xb[r0 * XPITCH + s * 8 + tc];
                A[mt].y = xb[(r0 + 8) * XPITCH + s * 8 + tc];
                A[mt].z = xb[r0 * XPITCH + s * 8 + tc + 4];
                A[mt].w = xb[(r0 + 8) * XPITCH + s * 8 + tc + 4];
            }
            #pragma unroll
            for (int t1 = 0; t1 < 8; t1++) {
                uint2 Bv = *reinterpret_cast<const uint2*>(
                    sm + W1F_U + ((((nh * 8 + t1) * 8 + s) * 32) + lid) * 2);
                mma8(C1[0][t1], A[0], Bv);
                mma8(C1[1][t1], A[1], Bv);
            }
        }

        // ---- transform in place: bias + ELU -> tf32 bits ----
        #pragma unroll
        for (int mt = 0; mt < 2; mt++)
            #pragma unroll
            for (int t1 = 0; t1 < 8; t1++) {
                int colA = nh * 64 + t1 * 8 + 2 * tc;
                float bA = b1s[colA], bB = b1s[colA + 1];
                C1[mt][t1][0] = __uint_as_float(f2tf32(eluf(C1[mt][t1][0] + bA)));
                C1[mt][t1][1] = __uint_as_float(f2tf32(eluf(C1[mt][t1][1] + bB)));
                C1[mt][t1][2] = __uint_as_float(f2tf32(eluf(C1[mt][t1][2] + bA)));
                C1[mt][t1][3] = __uint_as_float(f2tf32(eluf(C1[mt][t1][3] + bB)));
            }

        __syncthreads();   // (c) all x reads done; XH becomes h quarter buffers

        // h quarter q covers hid cols [32q, 32q+32), owned by warps nh == q>>1.
        // processing order q: 0, 2, 1, 3 ; regions ping-pong 0,1,0,1.
        // store q0 -> region 0
        #pragma unroll
        for (int pre = 0; pre < 1; pre++) {
            if (nh == 0) {
                uint32_t* hb = sm + XH_U;          // region 0
                #pragma unroll
                for (int tt = 0; tt < 4; tt++)
                    #pragma unroll
                    for (int mt = 0; mt < 2; mt++) {
                        int r0 = mg * 32 + mt * 16 + g;
                        int lc = tt * 8 + 2 * tc;
                        uint2 lo, hi;
                        lo.x = __float_as_uint(C1[mt][tt][0]);
                        lo.y = __float_as_uint(C1[mt][tt][1]);
                        hi.x = __float_as_uint(C1[mt][tt][2]);
                        hi.y = __float_as_uint(C1[mt][tt][3]);
                        *reinterpret_cast<uint2*>(hb + r0 * HPITCH + lc) = lo;
                        *reinterpret_cast<uint2*>(hb + (r0 + 8) * HPITCH + lc) = hi;
                    }
            }
        }
        __syncthreads();   // (d)

        float C2[2][4][4];
        #pragma unroll
        for (int mt = 0; mt < 2; mt++)
            #pragma unroll
            for (int t2 = 0; t2 < 4; t2++)
                #pragma unroll
                for (int r = 0; r < 4; r++) C2[mt][t2][r] = 0.0f;

        const int qorder[4] = {0, 2, 1, 3};
        #pragma unroll
        for (int k = 0; k < 4; k++) {
            const int qk = qorder[k];
            const int creg = k & 1;                // region holding quarter qk

            // store next quarter into the other region (overlaps with MMA below)
            if (k < 3) {
                const int qn = qorder[k + 1];
                if (nh == (qn >> 1)) {
                    uint32_t* hb = sm + XH_U + ((k + 1) & 1) * HREG_U;
                    const int t1b = (qn & 1) * 4;
                    #pragma unroll
                    for (int tt = 0; tt < 4; tt++)
                        #pragma unroll
                        for (int mt = 0; mt < 2; mt++) {
                            int t1 = t1b + tt;
                            int r0 = mg * 32 + mt * 16 + g;
                            int lc = tt * 8 + 2 * tc;
                            uint2 lo, hi;
                            lo.x = __float_as_uint(C1[mt][t1][0]);
                            lo.y = __float_as_uint(C1[mt][t1][1]);
                            hi.x = __float_as_uint(C1[mt][t1][2]);
                            hi.y = __float_as_uint(C1[mt][t1][3]);
                            *reinterpret_cast<uint2*>(hb + r0 * HPITCH + lc) = lo;
                            *reinterpret_cast<uint2*>(hb + (r0 + 8) * HPITCH + lc) = hi;
                        }
                }
            }

            // GEMM2 over quarter qk: ksteps s2 = 4*qk + sl
            const uint32_t* hb = sm + XH_U + creg * HREG_U;
            #pragma unroll
            for (int sl = 0; sl < 4; sl++) {
                int s2 = qk * 4 + sl;
                uint4 A[2];
                #pragma unroll
                for (int mt = 0; mt < 2; mt++) {
                    int r0 = mg * 32 + mt * 16 + g;
                    A[mt].x = hb[r0 * HPITCH + sl * 8 + tc];
                    A[mt].y = hb[(r0 + 8) * HPITCH + sl * 8 + tc];
                    A[mt].z = hb[r0 * HPITCH + sl * 8 + tc + 4];
                    A[mt].w = hb[(r0 + 8) * HPITCH + sl * 8 + tc + 4];
                }
                #pragma unroll
                for (int t2 = 0; t2 < 4; t2++) {
                    uint2 Bv = *reinterpret_cast<const uint2*>(
                        sm + W2F_U + ((((nh * 4 + t2) * 16 + s2) * 32) + lid) * 2);
                    mma8(C2[0][t2], A[0], Bv);
                    mma8(C2[1][t2], A[1], Bv);
                }
            }
            __syncthreads();
        }

        // ---- epilogue2: + b2 -> out[b, head, :] ----
        #pragma unroll
        for (int mt = 0; mt < 2; mt++) {
            const size_t rbase = mbase + (size_t)rep * MT + mg * 32 + mt * 16 + g;
            #pragma unroll
            for (int half = 0; half < 2; half++) {
                const size_t off = (rbase + 8 * half) * (NHEAD * OUT_SZ)
                                 + (size_t)head * OUT_SZ;
                #pragma unroll
                for (int t2 = 0; t2 < 4; t2++) {
                    int col = nh * 32 + t2 * 8 + 2 * tc;
                    float2 o;
                    o.x = C2[mt][t2][half * 2 + 0] + b2s[col];
                    o.y = C2[mt][t2][half * 2 + 1] + b2s[col + 1];
                    *reinterpret_cast<float2*>(out + off + col) = o;
                }
            }
        }
    }
}

// ---------------- launch ----------------
extern "C" void kernel_launch(void* const* d_in, const int* in_sizes, int n_in,
                              void* d_out, int out_size)
{
    const float* x  = (const float*)d_in[0];
    const float* W1 = (const float*)d_in[1];
    const float* b1 = (const float*)d_in[2];
    const float* W2 = (const float*)d_in[3];
    const float* b2 = (const float*)d_in[4];
    float* out = (float*)d_out;

    int B = in_sizes[0] / IN_SZ;            // 131072
    int ytiles = B / (MT * REPS);           // 256

    cudaFuncSetAttribute(mlp16_kernel,
                         cudaFuncAttributeMaxDynamicSharedMemorySize, SMEM_BYTES);
    mlp16_kernel<<<dim3(NHEAD, ytiles), NTHREADS, SMEM_BYTES>>>(x, W1, b1, W2, b2, out);
}